// round 12
// baseline (speedup 1.0000x reference)
#include <cuda_runtime.h>
#include <cuda_fp16.h>
#include <cstdint>

#define BB 4096
#define II 256
#define OO 256
#define EE 8
#define NRB 128         // router blocks
#define ROWS_PB 32      // rows per router block
#define TSTRIDE 18

// ---------------------------------------------------------------------------
// Device scratch (no allocations allowed). NO persistent state: every launch
// overwrites all of g_blkcnt and the used prefix of g_rowlist (plain stores,
// no atomics, nothing to reset) -> replay-safe by construction.
// ---------------------------------------------------------------------------
__device__ __align__(16) int g_blkcnt[EE * NRB];            // [e*128 + b]
__device__ int g_rowlist[EE * NRB * ROWS_PB];               // [(e*128+b)*32 + j]
__device__ __half g_xh[BB * II];
__device__ __half g_xl[BB * II];
__device__ __half g_wh[EE * OO * II];                        // transposed: [e][o][i]

__device__ __forceinline__ uint32_t smem_to_u32(const void* p) {
    uint32_t a;
    asm("{ .reg .u64 t; cvta.to.shared.u64 t, %1; cvt.u32.u64 %0, t; }" : "=r"(a) : "l"(p));
    return a;
}
__device__ __forceinline__ void cp16(uint32_t dst, const void* src) {
    asm volatile("cp.async.cg.shared.global [%0], [%1], 16;" :: "r"(dst), "l"(src));
}
// D += A*B, m16n8k16 fp16 -> f32
#define MMAF16(d, a, b) \
    asm volatile( \
        "mma.sync.aligned.m16n8k16.row.col.f32.f16.f16.f32 " \
        "{%0,%1,%2,%3}, {%4,%5,%6,%7}, {%8,%9}, {%0,%1,%2,%3};" \
        : "+f"((d)[0]), "+f"((d)[1]), "+f"((d)[2]), "+f"((d)[3]) \
        : "r"((a)[0]), "r"((a)[1]), "r"((a)[2]), "r"((a)[3]), \
          "r"((b)[0]), "r"((b)[1]))

__device__ __forceinline__ unsigned pkh(__half a, __half b) {
    __half2 t(a, b);
    return *reinterpret_cast<unsigned*>(&t);
}
__device__ __forceinline__ void splith4(float4 v, uint2& h, uint2& l) {
    __half h0 = __float2half_rn(v.x), h1 = __float2half_rn(v.y);
    __half h2 = __float2half_rn(v.z), h3 = __float2half_rn(v.w);
    __half l0 = __float2half_rn(v.x - __half2float(h0));
    __half l1 = __float2half_rn(v.y - __half2float(h1));
    __half l2 = __float2half_rn(v.z - __half2float(h2));
    __half l3 = __float2half_rn(v.w - __half2float(h3));
    h.x = pkh(h0, h1); h.y = pkh(h2, h3);
    l.x = pkh(l0, l1); l.y = pkh(l2, l3);
}

// ---------------------------------------------------------------------------
// Prep: 144 blocks (one wave). Blocks 0..127: router, 32 rows each (+x fp16
// split). Blocks 128..143: W fp16 convert+transpose, 4 (e, o-slice) units each.
// All counts/rows written with plain stores.
// ---------------------------------------------------------------------------
__global__ __launch_bounds__(256) void prep_kernel(const float* __restrict__ x,
                                                   const float* __restrict__ W,
                                                   const float* __restrict__ Wp,
                                                   const float* __restrict__ bp,
                                                   float* __restrict__ y) {
    __shared__ float s_wp[EE * II];          // 8KB
    __shared__ float s_bp[EE];
    __shared__ int s_cnt[EE];
    __shared__ int s_list[EE][ROWS_PB];      // 1KB
    __shared__ float s_t[256][33];           // 33.8KB (W path)

    int tid = threadIdx.x;
    int bx = blockIdx.x;

    if (bx >= NRB) {
        // ---- W conversion: W[e][i][o] fp32 -> g_wh [e][o][i] fp16 ----
        int b = bx - NRB;                    // 0..15
#pragma unroll 1
        for (int si = 0; si < 4; si++) {
            int s = b * 4 + si;              // 0..63
            int e = s >> 3;
            int o0 = (s & 7) * 32;
            const float* wb = W + (size_t)e * II * OO;
#pragma unroll
            for (int j = 0; j < 8; j++) {
                float4 v = *reinterpret_cast<const float4*>(&wb[(size_t)tid * OO + o0 + j * 4]);
                s_t[tid][j * 4 + 0] = v.x; s_t[tid][j * 4 + 1] = v.y;
                s_t[tid][j * 4 + 2] = v.z; s_t[tid][j * 4 + 3] = v.w;
            }
            __syncthreads();
            int ol = tid >> 3;               // 0..31 -> out row o0+ol
            int i0 = (tid & 7) * 32;         // 32 consecutive i
            unsigned hp[16];
#pragma unroll
            for (int j = 0; j < 16; j++) {
                float a = s_t[i0 + 2 * j][ol];
                float c = s_t[i0 + 2 * j + 1][ol];
                hp[j] = pkh(__float2half_rn(a), __float2half_rn(c));
            }
            size_t base = ((size_t)e * OO + o0 + ol) * II + i0;
            uint4* dh = reinterpret_cast<uint4*>(g_wh + base);
#pragma unroll
            for (int q = 0; q < 4; q++)
                dh[q] = make_uint4(hp[q * 4], hp[q * 4 + 1], hp[q * 4 + 2], hp[q * 4 + 3]);
            __syncthreads();                 // guard s_t reuse
        }
        return;
    }

    // ---- Router (validated logic, 32 rows/block) + x fp16 split ----
    {
        const float4* Wp4 = reinterpret_cast<const float4*>(Wp);
        float4* swp4 = reinterpret_cast<float4*>(s_wp);
#pragma unroll
        for (int i = 0; i < 2; i++) swp4[tid + 256 * i] = Wp4[tid + 256 * i];
    }
    if (tid < EE) { s_bp[tid] = bp[tid]; s_cnt[tid] = 0; }
    __syncthreads();

    int warp = tid >> 5;
    int lane = tid & 31;
    int e_lane = lane >> 2;
    const float4* X4 = reinterpret_cast<const float4*>(x);
    float4* Y4 = reinterpret_cast<float4*>(y);

#pragma unroll 2
    for (int i = 0; i < 4; i++) {
        int row = bx * ROWS_PB + warp * 4 + i;
        float4 xa = X4[row * 64 + lane];
        float4 xb = X4[row * 64 + 32 + lane];

        {   // emit fp16 hi/lo split of x
            uint2 ha, la, hb, lb;
            splith4(xa, ha, la);
            splith4(xb, hb, lb);
            *reinterpret_cast<uint2*>(g_xh + (size_t)row * II + lane * 4) = ha;
            *reinterpret_cast<uint2*>(g_xl + (size_t)row * II + lane * 4) = la;
            *reinterpret_cast<uint2*>(g_xh + (size_t)row * II + 128 + lane * 4) = hb;
            *reinterpret_cast<uint2*>(g_xl + (size_t)row * II + 128 + lane * 4) = lb;
        }

        float p[EE];
#pragma unroll
        for (int e = 0; e < EE; e++) {
            const float4* we = reinterpret_cast<const float4*>(s_wp + e * II);
            float4 wa = we[lane];
            float4 wb2 = we[32 + lane];
            p[e] = xa.x * wa.x + xa.y * wa.y + xa.z * wa.z + xa.w * wa.w
                 + xb.x * wb2.x + xb.y * wb2.y + xb.z * wb2.z + xb.w * wb2.w;
        }
#pragma unroll
        for (int s = 16; s >= 4; s >>= 1)
#pragma unroll
            for (int e = 0; e < EE; e++)
                p[e] += __shfl_xor_sync(0xffffffffu, p[e], s);
        float v = p[0];
#pragma unroll
        for (int j = 1; j < EE; j++) v = (e_lane == j) ? p[j] : v;
        v += __shfl_xor_sync(0xffffffffu, v, 1);
        v += __shfl_xor_sync(0xffffffffu, v, 2);

        float z = v + s_bp[e_lane];
        float g = 1.0f / (1.0f + expf(-z));

        float m = g;
        m = fmaxf(m, __shfl_xor_sync(0xffffffffu, m, 4));
        m = fmaxf(m, __shfl_xor_sync(0xffffffffu, m, 8));
        m = fmaxf(m, __shfl_xor_sync(0xffffffffu, m, 16));

        unsigned bal = __ballot_sync(0xffffffffu, g == m);
        int nsel = __popc(bal & 0x11111111u);

        if ((g == m) && ((lane & 3) == 0)) {
            int pos = atomicAdd(&s_cnt[e_lane], 1);    // smem atomic only
            s_list[e_lane][pos] = row | (nsel > 1 ? 0x40000000 : 0);
        }
        if (nsel > 1) {     // tied rows summed via gmem atomicAdd in gemm
            Y4[row * 64 + lane] = make_float4(0.f, 0.f, 0.f, 0.f);
            Y4[row * 64 + 32 + lane] = make_float4(0.f, 0.f, 0.f, 0.f);
        }
    }
    __syncthreads();

    // Plain stores: all 8 counts per block written every launch.
    if (tid < EE) g_blkcnt[tid * NRB + bx] = s_cnt[tid];
    if (warp < EE) {
        int n = s_cnt[warp];
        if (lane < n)
            g_rowlist[(warp * NRB + bx) * ROWS_PB + lane] = s_list[warp][lane];
    }
}

// ---------------------------------------------------------------------------
// mma.sync GEMM, fp16 2-term: y = (xh + xl) * wh. grid (EE, 18) = 144 blocks,
// one wave; block (e, t0) tile-strides (32 gathered rows x 256 cols / tile).
// Row offsets reconstructed via shfl prefix-scan over g_blkcnt (no atomics).
// K in 4 chunks of 64, TRIPLE-buffered smem fed by cp.async.
// ---------------------------------------------------------------------------
#define AP 72                        // padded row stride (halfs): 144B
#define ABYTES (32 * AP * 2)         // 4608
#define BBYTES_T (256 * AP * 2)      // 36864
#define CHUNKB (2 * ABYTES + BBYTES_T)      // 46080: Ah | Al | Bh
#define SM_HDR 1024
#define SMEM_GEMM (SM_HDR + 3 * CHUNKB)     // 139264

__global__ __launch_bounds__(256) void gemm_kernel(float* __restrict__ y) {
    extern __shared__ char smem[];
    int tid = threadIdx.x, wid = tid >> 5, lane = tid & 31;
    int gid = lane >> 2, tig = lane & 3;
    int e = blockIdx.x;
    int t0 = blockIdx.y;

    int* rowids = reinterpret_cast<int*>(smem);          // 32 ints
    int* s_p = reinterpret_cast<int*>(smem + 256);       // 129 ints

    // Prefix scan over the 128 per-block counts of expert e.
    if (tid < 32) {
        int4 v = reinterpret_cast<const int4*>(g_blkcnt + e * NRB)[tid];
        int s = v.x + v.y + v.z + v.w;
        int inc = s;
#pragma unroll
        for (int d = 1; d < 32; d <<= 1) {
            int n = __shfl_up_sync(0xffffffffu, inc, d);
            if (lane >= d) inc += n;
        }
        int ex = inc - s;
        s_p[4 * tid + 0] = ex;
        s_p[4 * tid + 1] = ex + v.x;
        s_p[4 * tid + 2] = ex + v.x + v.y;
        s_p[4 * tid + 3] = ex + v.x + v.y + v.z;
        if (tid == 31) s_p[128] = inc;
    }
    __syncthreads();
    int count = s_p[128];

    uint32_t sb = smem_to_u32(smem);
    const __half* wh = g_wh + (size_t)e * OO * II;

#pragma unroll 1
    for (int tile = t0; tile * 32 < count; tile += TSTRIDE) {
        __syncthreads();    // guard rowids reuse across tile iterations
        if (tid < 32) {
            int g = tile * 32 + tid;
            int rv = -1;
            if (g < count) {
                int lo = 0, hi = 128;
#pragma unroll
                for (int st = 0; st < 7; st++) {
                    int mid = (lo + hi) >> 1;
                    if (s_p[mid] <= g) lo = mid; else hi = mid;
                }
                rv = g_rowlist[(e * NRB + lo) * ROWS_PB + (g - s_p[lo])];
            }
            rowids[tid] = rv;
        }
        __syncthreads();

        int ar = tid >> 3;                       // A row 0..31
        int ac = tid & 7;                        // 16B chunk 0..7
        int rvA = rowids[ar];
        int ridA = (rvA < 0) ? 0 : (rvA & 0x3FFFFFFF);
        const __half* xh = g_xh + (size_t)ridA * II;
        const __half* xl = g_xl + (size_t)ridA * II;

        auto load_chunk = [&](int c, int b) {
            uint32_t base = sb + SM_HDR + b * CHUNKB;
            int kc = c * 64;
            uint32_t offA = ar * 144 + ac * 16;
            cp16(base + offA, xh + kc + ac * 8);
            cp16(base + ABYTES + offA, xl + kc + ac * 8);
#pragma unroll
            for (int j = 0; j < 8; j++) {
                int n = (tid >> 3) + j * 32;
                cp16(base + 2 * ABYTES + n * 144 + ac * 16, wh + (size_t)n * II + kc + ac * 8);
            }
            asm volatile("cp.async.commit_group;" ::: "memory");
        };

        float d[2][4][4];
#pragma unroll
        for (int mt = 0; mt < 2; mt++)
#pragma unroll
            for (int nt = 0; nt < 4; nt++)
#pragma unroll
                for (int q = 0; q < 4; q++) d[mt][nt][q] = 0.f;

        load_chunk(0, 0);
        load_chunk(1, 1);

#pragma unroll
        for (int c = 0; c < 4; c++) {
            if (c < 2) {
                load_chunk(c + 2, (c + 2) % 3);
                asm volatile("cp.async.wait_group 2;" ::: "memory");
            } else if (c == 2) {
                asm volatile("cp.async.wait_group 1;" ::: "memory");
            } else {
                asm volatile("cp.async.wait_group 0;" ::: "memory");
            }
            __syncthreads();

            const char* bufp = smem + SM_HDR + (c % 3) * CHUNKB;
            const __half* Ah = reinterpret_cast<const __half*>(bufp);
            const __half* Al = reinterpret_cast<const __half*>(bufp + ABYTES);
            const __half* Bh = reinterpret_cast<const __half*>(bufp + 2 * ABYTES);

#pragma unroll
            for (int ks = 0; ks < 4; ks++) {
                int k0 = ks * 16 + 2 * tig;
                uint32_t ah[2][4], al[2][4];
#pragma unroll
                for (int mt = 0; mt < 2; mt++) {
                    const __half* r0 = Ah + (mt * 16 + gid) * AP;
                    const __half* r1 = r0 + 8 * AP;
                    ah[mt][0] = *reinterpret_cast<const uint32_t*>(r0 + k0);
                    ah[mt][1] = *reinterpret_cast<const uint32_t*>(r1 + k0);
                    ah[mt][2] = *reinterpret_cast<const uint32_t*>(r0 + k0 + 8);
                    ah[mt][3] = *reinterpret_cast<const uint32_t*>(r1 + k0 + 8);
                    const __half* s0 = Al + (mt * 16 + gid) * AP;
                    const __half* s1 = s0 + 8 * AP;
                    al[mt][0] = *reinterpret_cast<const uint32_t*>(s0 + k0);
                    al[mt][1] = *reinterpret_cast<const uint32_t*>(s1 + k0);
                    al[mt][2] = *reinterpret_cast<const uint32_t*>(s0 + k0 + 8);
                    al[mt][3] = *reinterpret_cast<const uint32_t*>(s1 + k0 + 8);
                }
#pragma unroll
                for (int nt = 0; nt < 4; nt++) {
                    int nrow = wid * 32 + nt * 8 + gid;
                    const __half* bh_p = Bh + nrow * AP;
                    uint32_t bh[2] = {*reinterpret_cast<const uint32_t*>(bh_p + k0),
                                      *reinterpret_cast<const uint32_t*>(bh_p + k0 + 8)};
#pragma unroll
                    for (int mt = 0; mt < 2; mt++) {
                        MMAF16(d[mt][nt], ah[mt], bh);   // xh * wh
                        MMAF16(d[mt][nt], al[mt], bh);   // xl * wh
                    }
                }
            }
            __syncthreads();
        }

        // Epilogue: scatter D fragments
#pragma unroll
        for (int mt = 0; mt < 2; mt++) {
#pragma unroll
            for (int h = 0; h < 2; h++) {
                int rr = mt * 16 + gid + h * 8;
                int rv = rowids[rr];
                if (rv < 0) continue;
                int rid = rv & 0x3FFFFFFF;
                bool multi = (rv & 0x40000000) != 0;
                float* yp = y + (size_t)rid * OO + wid * 32 + 2 * tig;
                if (multi) {
#pragma unroll
                    for (int nt = 0; nt < 4; nt++) {
                        atomicAdd(&yp[nt * 8], d[mt][nt][h * 2 + 0]);
                        atomicAdd(&yp[nt * 8 + 1], d[mt][nt][h * 2 + 1]);
                    }
                } else {
#pragma unroll
                    for (int nt = 0; nt < 4; nt++)
                        *reinterpret_cast<float2*>(&yp[nt * 8]) =
                            make_float2(d[mt][nt][h * 2 + 0], d[mt][nt][h * 2 + 1]);
                }
            }
        }
    }
}

extern "C" void kernel_launch(void* const* d_in, const int* in_sizes, int n_in,
                              void* d_out, int out_size) {
    const float* x  = (const float*)d_in[0];
    const float* W  = (const float*)d_in[1];
    const float* Wp = (const float*)d_in[2];
    const float* bp = (const float*)d_in[3];
    float* y = (float*)d_out;

    cudaFuncSetAttribute(gemm_kernel, cudaFuncAttributeMaxDynamicSharedMemorySize, SMEM_GEMM);
    prep_kernel<<<144, 256>>>(x, W, Wp, bp, y);
    gemm_kernel<<<dim3(EE, TSTRIDE), 256, SMEM_GEMM>>>(y);
}

// round 13
// speedup vs baseline: 1.3861x; 1.3861x over previous
#include <cuda_runtime.h>
#include <cuda_fp16.h>
#include <cstdint>

#define BB 4096
#define II 256
#define OO 256
#define EE 8
#define NRB 128         // router blocks
#define ROWS_PB 32      // rows per router block
#define TSTRIDE 18

// ---------------------------------------------------------------------------
// Device scratch (no allocations allowed). NO persistent state: every launch
// overwrites all of g_blkcnt and the used prefix of g_rowlist (plain stores,
// no atomics, nothing to reset) -> replay-safe by construction.
// ---------------------------------------------------------------------------
__device__ __align__(16) int g_blkcnt[EE * NRB];            // [e*128 + b]
__device__ int g_rowlist[EE * NRB * ROWS_PB];               // [(e*128+b)*32 + j]
__device__ __half g_xh[BB * II];
__device__ __half g_xl[BB * II];
__device__ __half g_wh[EE * OO * II];                        // transposed: [e][o][i]

__device__ __forceinline__ uint32_t smem_to_u32(const void* p) {
    uint32_t a;
    asm("{ .reg .u64 t; cvta.to.shared.u64 t, %1; cvt.u32.u64 %0, t; }" : "=r"(a) : "l"(p));
    return a;
}
__device__ __forceinline__ void cp16(uint32_t dst, const void* src) {
    asm volatile("cp.async.cg.shared.global [%0], [%1], 16;" :: "r"(dst), "l"(src));
}
// D += A*B, m16n8k16 fp16 -> f32
#define MMAF16(d, a, b) \
    asm volatile( \
        "mma.sync.aligned.m16n8k16.row.col.f32.f16.f16.f32 " \
        "{%0,%1,%2,%3}, {%4,%5,%6,%7}, {%8,%9}, {%0,%1,%2,%3};" \
        : "+f"((d)[0]), "+f"((d)[1]), "+f"((d)[2]), "+f"((d)[3]) \
        : "r"((a)[0]), "r"((a)[1]), "r"((a)[2]), "r"((a)[3]), \
          "r"((b)[0]), "r"((b)[1]))

__device__ __forceinline__ unsigned pkh(__half a, __half b) {
    __half2 t(a, b);
    return *reinterpret_cast<unsigned*>(&t);
}
__device__ __forceinline__ void splith4(float4 v, uint2& h, uint2& l) {
    __half h0 = __float2half_rn(v.x), h1 = __float2half_rn(v.y);
    __half h2 = __float2half_rn(v.z), h3 = __float2half_rn(v.w);
    __half l0 = __float2half_rn(v.x - __half2float(h0));
    __half l1 = __float2half_rn(v.y - __half2float(h1));
    __half l2 = __float2half_rn(v.z - __half2float(h2));
    __half l3 = __float2half_rn(v.w - __half2float(h3));
    h.x = pkh(h0, h1); h.y = pkh(h2, h3);
    l.x = pkh(l0, l1); l.y = pkh(l2, l3);
}

// ---------------------------------------------------------------------------
// Prep: 192 blocks, all parallel (no serial unit loops).
// Blocks 0..127: router, 32 rows each (+x fp16 split).
// Blocks 128..191: W fp16 convert+transpose, ONE (e, o-slice) unit each.
// All counts/rows written with plain stores.
// ---------------------------------------------------------------------------
__global__ __launch_bounds__(256) void prep_kernel(const float* __restrict__ x,
                                                   const float* __restrict__ W,
                                                   const float* __restrict__ Wp,
                                                   const float* __restrict__ bp,
                                                   float* __restrict__ y) {
    __shared__ float s_wp[EE * II];          // 8KB
    __shared__ float s_bp[EE];
    __shared__ int s_cnt[EE];
    __shared__ int s_list[EE][ROWS_PB];      // 1KB
    __shared__ float s_t[256][33];           // 33.8KB (W path)

    int tid = threadIdx.x;
    int bx = blockIdx.x;

    if (bx >= NRB) {
        // ---- W conversion: W[e][i][o] fp32 -> g_wh [e][o][i] fp16 ----
        int s = bx - NRB;                    // 0..63
        int e = s >> 3;
        int o0 = (s & 7) * 32;
        const float* wb = W + (size_t)e * II * OO;
#pragma unroll
        for (int j = 0; j < 8; j++) {
            float4 v = *reinterpret_cast<const float4*>(&wb[(size_t)tid * OO + o0 + j * 4]);
            s_t[tid][j * 4 + 0] = v.x; s_t[tid][j * 4 + 1] = v.y;
            s_t[tid][j * 4 + 2] = v.z; s_t[tid][j * 4 + 3] = v.w;
        }
        __syncthreads();
        int ol = tid >> 3;                   // 0..31 -> out row o0+ol
        int i0 = (tid & 7) * 32;             // 32 consecutive i
        unsigned hp[16];
#pragma unroll
        for (int j = 0; j < 16; j++) {
            float a = s_t[i0 + 2 * j][ol];
            float c = s_t[i0 + 2 * j + 1][ol];
            hp[j] = pkh(__float2half_rn(a), __float2half_rn(c));
        }
        size_t base = ((size_t)e * OO + o0 + ol) * II + i0;
        uint4* dh = reinterpret_cast<uint4*>(g_wh + base);
#pragma unroll
        for (int q = 0; q < 4; q++)
            dh[q] = make_uint4(hp[q * 4], hp[q * 4 + 1], hp[q * 4 + 2], hp[q * 4 + 3]);
        return;
    }

    // ---- Router (validated logic, 32 rows/block) + x fp16 split ----
    {
        const float4* Wp4 = reinterpret_cast<const float4*>(Wp);
        float4* swp4 = reinterpret_cast<float4*>(s_wp);
#pragma unroll
        for (int i = 0; i < 2; i++) swp4[tid + 256 * i] = Wp4[tid + 256 * i];
    }
    if (tid < EE) { s_bp[tid] = bp[tid]; s_cnt[tid] = 0; }
    __syncthreads();

    int warp = tid >> 5;
    int lane = tid & 31;
    int e_lane = lane >> 2;
    const float4* X4 = reinterpret_cast<const float4*>(x);
    float4* Y4 = reinterpret_cast<float4*>(y);

#pragma unroll 2
    for (int i = 0; i < 4; i++) {
        int row = bx * ROWS_PB + warp * 4 + i;
        float4 xa = X4[row * 64 + lane];
        float4 xb = X4[row * 64 + 32 + lane];

        {   // emit fp16 hi/lo split of x
            uint2 ha, la, hb, lb;
            splith4(xa, ha, la);
            splith4(xb, hb, lb);
            *reinterpret_cast<uint2*>(g_xh + (size_t)row * II + lane * 4) = ha;
            *reinterpret_cast<uint2*>(g_xl + (size_t)row * II + lane * 4) = la;
            *reinterpret_cast<uint2*>(g_xh + (size_t)row * II + 128 + lane * 4) = hb;
            *reinterpret_cast<uint2*>(g_xl + (size_t)row * II + 128 + lane * 4) = lb;
        }

        float p[EE];
#pragma unroll
        for (int e = 0; e < EE; e++) {
            const float4* we = reinterpret_cast<const float4*>(s_wp + e * II);
            float4 wa = we[lane];
            float4 wb2 = we[32 + lane];
            p[e] = xa.x * wa.x + xa.y * wa.y + xa.z * wa.z + xa.w * wa.w
                 + xb.x * wb2.x + xb.y * wb2.y + xb.z * wb2.z + xb.w * wb2.w;
        }
#pragma unroll
        for (int s = 16; s >= 4; s >>= 1)
#pragma unroll
            for (int e = 0; e < EE; e++)
                p[e] += __shfl_xor_sync(0xffffffffu, p[e], s);
        float v = p[0];
#pragma unroll
        for (int j = 1; j < EE; j++) v = (e_lane == j) ? p[j] : v;
        v += __shfl_xor_sync(0xffffffffu, v, 1);
        v += __shfl_xor_sync(0xffffffffu, v, 2);

        float z = v + s_bp[e_lane];
        float g = 1.0f / (1.0f + expf(-z));

        float m = g;
        m = fmaxf(m, __shfl_xor_sync(0xffffffffu, m, 4));
        m = fmaxf(m, __shfl_xor_sync(0xffffffffu, m, 8));
        m = fmaxf(m, __shfl_xor_sync(0xffffffffu, m, 16));

        unsigned bal = __ballot_sync(0xffffffffu, g == m);
        int nsel = __popc(bal & 0x11111111u);

        if ((g == m) && ((lane & 3) == 0)) {
            int pos = atomicAdd(&s_cnt[e_lane], 1);    // smem atomic only
            s_list[e_lane][pos] = row | (nsel > 1 ? 0x40000000 : 0);
        }
        if (nsel > 1) {     // tied rows summed via gmem atomicAdd in gemm
            Y4[row * 64 + lane] = make_float4(0.f, 0.f, 0.f, 0.f);
            Y4[row * 64 + 32 + lane] = make_float4(0.f, 0.f, 0.f, 0.f);
        }
    }
    __syncthreads();

    // Plain stores: all 8 counts per block written every launch.
    if (tid < EE) g_blkcnt[tid * NRB + bx] = s_cnt[tid];
    if (warp < EE) {
        int n = s_cnt[warp];
        if (lane < n)
            g_rowlist[(warp * NRB + bx) * ROWS_PB + lane] = s_list[warp][lane];
    }
}

// ---------------------------------------------------------------------------
// mma.sync GEMM, fp16 2-term: y = (xh + xl) * wh.
// Tile = 32 gathered rows x 128 cols -> smem 84KB -> 2 CTAs/SM, 16 warps/SM.
// grid (16, 18) = 288 blocks (one wave at occ 2): x = e*2 + half, y = t0;
// block tile-strides by 18 over its expert's row tiles.
// Row offsets reconstructed via shfl prefix-scan over g_blkcnt (no atomics).
// K in 4 chunks of 64, triple-buffered smem fed by cp.async.
// ---------------------------------------------------------------------------
#define AP 72                        // padded row stride (halfs): 144B
#define ABYTES (32 * AP * 2)         // 4608
#define BBY (128 * AP * 2)           // 18432
#define CHUNKB (2 * ABYTES + BBY)    // 27648: Ah | Al | Bh
#define SM_HDR 1024
#define SMEM_GEMM (SM_HDR + 3 * CHUNKB)     // 83968 -> 2 CTAs/SM

__global__ __launch_bounds__(256, 2) void gemm_kernel(float* __restrict__ y) {
    extern __shared__ char smem[];
    int tid = threadIdx.x, wid = tid >> 5, lane = tid & 31;
    int gid = lane >> 2, tig = lane & 3;
    int e = blockIdx.x >> 1, half = blockIdx.x & 1;
    int t0 = blockIdx.y;

    int* rowids = reinterpret_cast<int*>(smem);          // 32 ints
    int* s_p = reinterpret_cast<int*>(smem + 256);       // 129 ints

    // Prefix scan over the 128 per-block counts of expert e.
    if (tid < 32) {
        int4 v = reinterpret_cast<const int4*>(g_blkcnt + e * NRB)[tid];
        int s = v.x + v.y + v.z + v.w;
        int inc = s;
#pragma unroll
        for (int d = 1; d < 32; d <<= 1) {
            int n = __shfl_up_sync(0xffffffffu, inc, d);
            if (lane >= d) inc += n;
        }
        int ex = inc - s;
        s_p[4 * tid + 0] = ex;
        s_p[4 * tid + 1] = ex + v.x;
        s_p[4 * tid + 2] = ex + v.x + v.y;
        s_p[4 * tid + 3] = ex + v.x + v.y + v.z;
        if (tid == 31) s_p[128] = inc;
    }
    __syncthreads();
    int count = s_p[128];

    uint32_t sb = smem_to_u32(smem);
    const __half* wh = g_wh + ((size_t)e * OO + half * 128) * II;

#pragma unroll 1
    for (int tile = t0; tile * 32 < count; tile += TSTRIDE) {
        __syncthreads();    // guard rowids reuse across tile iterations
        if (tid < 32) {
            int g = tile * 32 + tid;
            int rv = -1;
            if (g < count) {
                int lo = 0, hi = 128;
#pragma unroll
                for (int st = 0; st < 7; st++) {
                    int mid = (lo + hi) >> 1;
                    if (s_p[mid] <= g) lo = mid; else hi = mid;
                }
                rv = g_rowlist[(e * NRB + lo) * ROWS_PB + (g - s_p[lo])];
            }
            rowids[tid] = rv;
        }
        __syncthreads();

        int ar = tid >> 3;                       // A row 0..31
        int ac = tid & 7;                        // 16B chunk 0..7
        int rvA = rowids[ar];
        int ridA = (rvA < 0) ? 0 : (rvA & 0x3FFFFFFF);
        const __half* xh = g_xh + (size_t)ridA * II;
        const __half* xl = g_xl + (size_t)ridA * II;

        auto load_chunk = [&](int c, int b) {
            uint32_t base = sb + SM_HDR + b * CHUNKB;
            int kc = c * 64;
            uint32_t offA = ar * 144 + ac * 16;
            cp16(base + offA, xh + kc + ac * 8);
            cp16(base + ABYTES + offA, xl + kc + ac * 8);
#pragma unroll
            for (int j = 0; j < 4; j++) {
                int n = (tid >> 3) + j * 32;     // 0..127
                cp16(base + 2 * ABYTES + n * 144 + ac * 16, wh + (size_t)n * II + kc + ac * 8);
            }
            asm volatile("cp.async.commit_group;" ::: "memory");
        };

        float d[2][2][4];
#pragma unroll
        for (int mt = 0; mt < 2; mt++)
#pragma unroll
            for (int nt = 0; nt < 2; nt++)
#pragma unroll
                for (int q = 0; q < 4; q++) d[mt][nt][q] = 0.f;

        load_chunk(0, 0);
        load_chunk(1, 1);

#pragma unroll
        for (int c = 0; c < 4; c++) {
            if (c < 2) {
                load_chunk(c + 2, (c + 2) % 3);
                asm volatile("cp.async.wait_group 2;" ::: "memory");
            } else if (c == 2) {
                asm volatile("cp.async.wait_group 1;" ::: "memory");
            } else {
                asm volatile("cp.async.wait_group 0;" ::: "memory");
            }
            __syncthreads();

            const char* bufp = smem + SM_HDR + (c % 3) * CHUNKB;
            const __half* Ah = reinterpret_cast<const __half*>(bufp);
            const __half* Al = reinterpret_cast<const __half*>(bufp + ABYTES);
            const __half* Bh = reinterpret_cast<const __half*>(bufp + 2 * ABYTES);

#pragma unroll
            for (int ks = 0; ks < 4; ks++) {
                int k0 = ks * 16 + 2 * tig;
                uint32_t ah[2][4], al[2][4];
#pragma unroll
                for (int mt = 0; mt < 2; mt++) {
                    const __half* r0 = Ah + (mt * 16 + gid) * AP;
                    const __half* r1 = r0 + 8 * AP;
                    ah[mt][0] = *reinterpret_cast<const uint32_t*>(r0 + k0);
                    ah[mt][1] = *reinterpret_cast<const uint32_t*>(r1 + k0);
                    ah[mt][2] = *reinterpret_cast<const uint32_t*>(r0 + k0 + 8);
                    ah[mt][3] = *reinterpret_cast<const uint32_t*>(r1 + k0 + 8);
                    const __half* s0 = Al + (mt * 16 + gid) * AP;
                    const __half* s1 = s0 + 8 * AP;
                    al[mt][0] = *reinterpret_cast<const uint32_t*>(s0 + k0);
                    al[mt][1] = *reinterpret_cast<const uint32_t*>(s1 + k0);
                    al[mt][2] = *reinterpret_cast<const uint32_t*>(s0 + k0 + 8);
                    al[mt][3] = *reinterpret_cast<const uint32_t*>(s1 + k0 + 8);
                }
#pragma unroll
                for (int nt = 0; nt < 2; nt++) {
                    int nrow = wid * 16 + nt * 8 + gid;      // 0..127
                    const __half* bh_p = Bh + nrow * AP;
                    uint32_t bh[2] = {*reinterpret_cast<const uint32_t*>(bh_p + k0),
                                      *reinterpret_cast<const uint32_t*>(bh_p + k0 + 8)};
#pragma unroll
                    for (int mt = 0; mt < 2; mt++) {
                        MMAF16(d[mt][nt], ah[mt], bh);   // xh * wh
                        MMAF16(d[mt][nt], al[mt], bh);   // xl * wh
                    }
                }
            }
            __syncthreads();
        }

        // Epilogue: scatter D fragments (cols: half*128 + wid*16 + nt*8 + 2*tig)
#pragma unroll
        for (int mt = 0; mt < 2; mt++) {
#pragma unroll
            for (int h = 0; h < 2; h++) {
                int rr = mt * 16 + gid + h * 8;
                int rv = rowids[rr];
                if (rv < 0) continue;
                int rid = rv & 0x3FFFFFFF;
                bool multi = (rv & 0x40000000) != 0;
                float* yp = y + (size_t)rid * OO + half * 128 + wid * 16 + 2 * tig;
                if (multi) {
#pragma unroll
                    for (int nt = 0; nt < 2; nt++) {
                        atomicAdd(&yp[nt * 8], d[mt][nt][h * 2 + 0]);
                        atomicAdd(&yp[nt * 8 + 1], d[mt][nt][h * 2 + 1]);
                    }
                } else {
#pragma unroll
                    for (int nt = 0; nt < 2; nt++)
                        *reinterpret_cast<float2*>(&yp[nt * 8]) =
                            make_float2(d[mt][nt][h * 2 + 0], d[mt][nt][h * 2 + 1]);
                }
            }
        }
    }
}

extern "C" void kernel_launch(void* const* d_in, const int* in_sizes, int n_in,
                              void* d_out, int out_size) {
    const float* x  = (const float*)d_in[0];
    const float* W  = (const float*)d_in[1];
    const float* Wp = (const float*)d_in[2];
    const float* bp = (const float*)d_in[3];
    float* y = (float*)d_out;

    cudaFuncSetAttribute(gemm_kernel, cudaFuncAttributeMaxDynamicSharedMemorySize, SMEM_GEMM);
    prep_kernel<<<192, 256>>>(x, W, Wp, bp, y);
    gemm_kernel<<<dim3(16, TSTRIDE), 256, SMEM_GEMM>>>(y);
}